// round 16
// baseline (speedup 1.0000x reference)
#include <cuda_runtime.h>
#include <cuda_bf16.h>
#include <cstdint>
#include <cstddef>

// ---------------------------------------------------------------------------
// Problem constants
// ---------------------------------------------------------------------------
namespace {
constexpr int Bg    = 256;
constexpr int Hc    = 128;
constexpr int NRFc  = 16;
constexpr int NUSER = 4096;    // Bg*16
constexpr int NAG   = 16384;   // Bg*64
constexpr int APAD  = 136;     // bf16 elems per smem row
constexpr int ASTR  = APAD * 2; // 272 bytes
}

// ---------------------------------------------------------------------------
// Scratch (device globals — no allocation allowed)
// ---------------------------------------------------------------------------
__device__ float g_hu  [NUSER * Hc];
__device__ float g_ta  [NAG   * Hc];   // raw relu((noise+hag)@W_self_a + b1)
__device__ float g_t2  [NAG   * Hc];   // raw relu(ha2@W_self_a + b1)
__device__ float g_meanA [Bg * Hc];
__device__ float g_meanU [Bg * Hc];
__device__ float g_meanA2[Bg * Hc];
__device__ float g_hag [Bg * Hc];
// Pre-transposed + hi/lo-split weights: slots 0..5 = H x H, slot 6 = W_norm' (64x128 used)
__device__ __nv_bfloat16 g_wt_hi[7 * Hc * Hc];
__device__ __nv_bfloat16 g_wt_lo[7 * Hc * Hc];

// ---------------------------------------------------------------------------
// Helpers (verbatim R15)
// ---------------------------------------------------------------------------
__device__ __forceinline__ uint32_t smem_u32(const void* p) {
    uint32_t a;
    asm("{ .reg .u64 t; cvta.to.shared.u64 t, %1; cvt.u32.u64 %0, t; }"
        : "=r"(a) : "l"(p));
    return a;
}
__device__ __forceinline__ void ldsm4(uint32_t* r, uint32_t addr) {
    asm volatile("ldmatrix.sync.aligned.m8n8.x4.shared.b16 {%0,%1,%2,%3}, [%4];"
                 : "=r"(r[0]), "=r"(r[1]), "=r"(r[2]), "=r"(r[3]) : "r"(addr));
}
__device__ __forceinline__ void mma16816(float* d, const uint32_t* a, const uint32_t* b) {
    asm volatile(
        "mma.sync.aligned.m16n8k16.row.col.f32.bf16.bf16.f32 "
        "{%0,%1,%2,%3}, {%4,%5,%6,%7}, {%8,%9}, {%0,%1,%2,%3};"
        : "+f"(d[0]), "+f"(d[1]), "+f"(d[2]), "+f"(d[3])
        : "r"(a[0]), "r"(a[1]), "r"(a[2]), "r"(a[3]), "r"(b[0]), "r"(b[1]));
}
__device__ __forceinline__ uint32_t pack_bf2(__nv_bfloat16 a, __nv_bfloat16 b) {
    return (uint32_t)__bfloat16_as_ushort(a) | ((uint32_t)__bfloat16_as_ushort(b) << 16);
}
__device__ __forceinline__ void split2(float a, float b, uint32_t& hi, uint32_t& lo) {
    const __nv_bfloat16 h0 = __float2bfloat16(a), h1 = __float2bfloat16(b);
    hi = pack_bf2(h0, h1);
    lo = pack_bf2(__float2bfloat16(a - __bfloat162float(h0)),
                  __float2bfloat16(b - __bfloat162float(h1)));
}

// A tile load: fp32 (+optional broadcast add, group = row>>6), hi/lo split to smem
template<int TM, bool ADD>
__device__ __forceinline__ void load_split_A(const float* __restrict__ A,
                                             const float* __restrict__ addv,
                                             int row0, char* pAh, char* pAl, int tid)
{
    #pragma unroll
    for (int i = tid; i < TM * 16; i += 256) {
        const int r = i >> 4, k = (i & 15) * 8;
        const float* ap = A + (size_t)(row0 + r) * Hc + k;
        float v[8];
        *reinterpret_cast<float4*>(&v[0]) = *reinterpret_cast<const float4*>(ap);
        *reinterpret_cast<float4*>(&v[4]) = *reinterpret_cast<const float4*>(ap + 4);
        if (ADD) {
            const float* mp = addv + ((row0 + r) >> 6) * Hc + k;
            float m[8];
            *reinterpret_cast<float4*>(&m[0]) = *reinterpret_cast<const float4*>(mp);
            *reinterpret_cast<float4*>(&m[4]) = *reinterpret_cast<const float4*>(mp + 4);
            #pragma unroll
            for (int j = 0; j < 8; ++j) v[j] += m[j];
        }
        uint32_t hb[4], lb[4];
        #pragma unroll
        for (int j = 0; j < 4; ++j) split2(v[2*j], v[2*j+1], hb[j], lb[j]);
        const uint32_t o = (uint32_t)(r * ASTR + (i & 15) * 16);
        *reinterpret_cast<uint4*>(pAh + o) = *reinterpret_cast<uint4*>(hb);
        *reinterpret_cast<uint4*>(pAl + o) = *reinterpret_cast<uint4*>(lb);
    }
}

template<int NROWS>
__device__ __forceinline__ void load_B(const __nv_bfloat16* __restrict__ Wh,
                                       const __nv_bfloat16* __restrict__ Wl,
                                       char* pBh, char* pBl, int tid)
{
    const uint4* wh = reinterpret_cast<const uint4*>(Wh);
    const uint4* wl = reinterpret_cast<const uint4*>(Wl);
    #pragma unroll
    for (int i = tid; i < NROWS * 16; i += 256) {
        const uint32_t o = (uint32_t)((i >> 4) * ASTR + (i & 15) * 16);
        *reinterpret_cast<uint4*>(pBh + o) = wh[i];
        *reinterpret_cast<uint4*>(pBl + o) = wl[i];
    }
}

// 3-pass hi/lo MMA over K=128
template<int MF, int NF>
__device__ __forceinline__ void mma_3p(uint32_t aAh, uint32_t aAl,
                                       uint32_t aBh, uint32_t aBl,
                                       uint32_t a_off, uint32_t b_off,
                                       float (*acc)[NF][4])
{
    #pragma unroll
    for (int pass = 0; pass < 3; ++pass) {
        const uint32_t Ab = (pass == 2 ? aAl : aAh) + a_off;
        const uint32_t Bb = (pass == 1 ? aBl : aBh) + b_off;
        #pragma unroll
        for (int kc = 0; kc < 8; ++kc) {
            const uint32_t kb = (uint32_t)kc * 32;
            uint32_t af[MF][4];
            #pragma unroll
            for (int mf = 0; mf < MF; ++mf)
                ldsm4(af[mf], Ab + (uint32_t)(mf * 16 * ASTR) + kb);
            uint32_t bfr[NF][2];
            #pragma unroll
            for (int p = 0; p < NF / 2; ++p) {
                uint32_t t[4];
                ldsm4(t, Bb + (uint32_t)(p * 16 * ASTR) + kb);
                bfr[2*p][0] = t[0]; bfr[2*p][1] = t[1];
                bfr[2*p+1][0] = t[2]; bfr[2*p+1][1] = t[3];
            }
            #pragma unroll
            for (int mf = 0; mf < MF; ++mf)
                #pragma unroll
                for (int nf = 0; nf < NF; ++nf)
                    mma16816(acc[mf][nf], af[mf], bfr[nf]);
        }
    }
}
template<int MF>
__device__ __forceinline__ void zero4(float (*acc)[4][4]) {
    #pragma unroll
    for (int mf = 0; mf < MF; ++mf)
        #pragma unroll
        for (int nf = 0; nf < 4; ++nf)
            acc[mf][nf][0] = acc[mf][nf][1] = acc[mf][nf][2] = acc[mf][nf][3] = 0.f;
}

// epilogue: e = relu(acc+b) (+mean[g]) re-split into A tiles
template<int MF, bool ADDMEAN, int SHIFT>
__device__ __forceinline__ void epi_resplit(float (*acc)[4][4],
                                            const float* __restrict__ bias,
                                            const float* __restrict__ meanv,
                                            char* pAh, char* pAl,
                                            int row0, int m0, int n0, int lane)
{
    const int tq = lane & 3, gq = lane >> 2;
    #pragma unroll
    for (int mf = 0; mf < MF; ++mf) {
        const int r0 = m0 + mf * 16 + gq;
        const int g = ADDMEAN ? ((SHIFT == 6) ? ((row0 + m0) >> 6)
                                              : ((row0 + m0 + mf * 16) >> 4)) : 0;
        #pragma unroll
        for (int nf = 0; nf < 4; ++nf) {
            const int c = n0 + nf * 8 + 2 * tq;
            float mx = 0.f, my = 0.f;
            if (ADDMEAN) {
                const float2 mv = *reinterpret_cast<const float2*>(&meanv[g * Hc + c]);
                mx = mv.x; my = mv.y;
            }
            const float bb0 = bias[c], bb1 = bias[c + 1];
            const float e0 = fmaxf(acc[mf][nf][0] + bb0, 0.f) + mx;
            const float e1 = fmaxf(acc[mf][nf][1] + bb1, 0.f) + my;
            const float e2 = fmaxf(acc[mf][nf][2] + bb0, 0.f) + mx;
            const float e3 = fmaxf(acc[mf][nf][3] + bb1, 0.f) + my;
            uint32_t hi0, lo0, hi1, lo1;
            split2(e0, e1, hi0, lo0);
            split2(e2, e3, hi1, lo1);
            *reinterpret_cast<uint32_t*>(pAh + r0 * ASTR + c * 2) = hi0;
            *reinterpret_cast<uint32_t*>(pAl + r0 * ASTR + c * 2) = lo0;
            *reinterpret_cast<uint32_t*>(pAh + (r0 + 8) * ASTR + c * 2) = hi1;
            *reinterpret_cast<uint32_t*>(pAl + (r0 + 8) * ASTR + c * 2) = lo1;
        }
    }
}

// full-store epilogue: out[row][c] = relu(acc + b)
template<int MF>
__device__ __forceinline__ void epi_store(float (*acc)[4][4],
                                          const float* __restrict__ bias,
                                          float* __restrict__ outp,
                                          int row0, int m0, int n0, int lane)
{
    const int tq = lane & 3, gq = lane >> 2;
    #pragma unroll
    for (int mf = 0; mf < MF; ++mf) {
        const int row = row0 + m0 + mf * 16 + gq;
        #pragma unroll
        for (int nf = 0; nf < 4; ++nf) {
            const int c = n0 + nf * 8 + 2 * tq;
            const float bb0 = bias[c], bb1 = bias[c + 1];
            float2 lo, hi;
            lo.x = fmaxf(acc[mf][nf][0] + bb0, 0.f);
            lo.y = fmaxf(acc[mf][nf][1] + bb1, 0.f);
            hi.x = fmaxf(acc[mf][nf][2] + bb0, 0.f);
            hi.y = fmaxf(acc[mf][nf][3] + bb1, 0.f);
            *reinterpret_cast<float2*>(&outp[(size_t)row * Hc + c]) = lo;
            *reinterpret_cast<float2*>(&outp[(size_t)(row + 8) * Hc + c]) = hi;
        }
    }
}

// mean-16 epilogue
template<int MF>
__device__ __forceinline__ void epi_mean16(float (*acc)[4][4],
                                           const float* __restrict__ bias,
                                           float* __restrict__ outp,
                                           int row0, int m0, int n0, int lane)
{
    const int tq = lane & 3;
    #pragma unroll
    for (int mf = 0; mf < MF; ++mf) {
        const int grp = (row0 + m0 + mf * 16) >> 4;
        #pragma unroll
        for (int nf = 0; nf < 4; ++nf) {
            const int c = n0 + nf * 8 + 2 * tq;
            const float bb0 = bias[c], bb1 = bias[c + 1];
            float s0 = fmaxf(acc[mf][nf][0] + bb0, 0.f)
                     + fmaxf(acc[mf][nf][2] + bb0, 0.f);
            float s1 = fmaxf(acc[mf][nf][1] + bb1, 0.f)
                     + fmaxf(acc[mf][nf][3] + bb1, 0.f);
            s0 += __shfl_xor_sync(~0u, s0, 4);  s1 += __shfl_xor_sync(~0u, s1, 4);
            s0 += __shfl_xor_sync(~0u, s0, 8);  s1 += __shfl_xor_sync(~0u, s1, 8);
            s0 += __shfl_xor_sync(~0u, s0, 16); s1 += __shfl_xor_sync(~0u, s1, 16);
            if (lane < 4) {
                float2 o2 = {s0 * 0.0625f, s1 * 0.0625f};
                *reinterpret_cast<float2*>(&outp[grp * Hc + n0 + nf * 8 + 2 * lane]) = o2;
            }
        }
    }
}

// mean-64 epilogue (MF=4)
__device__ __forceinline__ void epi_mean64(float (*acc)[4][4],
                                           const float* __restrict__ bias,
                                           float* __restrict__ outp,
                                           int row0, int m0, int n0, int lane)
{
    const int tq = lane & 3;
    float s0[4] = {0,0,0,0}, s1[4] = {0,0,0,0};
    #pragma unroll
    for (int mf = 0; mf < 4; ++mf)
        #pragma unroll
        for (int nf = 0; nf < 4; ++nf) {
            const float bb0 = bias[n0 + nf * 8 + 2 * tq];
            const float bb1 = bias[n0 + nf * 8 + 2 * tq + 1];
            s0[nf] += fmaxf(acc[mf][nf][0] + bb0, 0.f)
                    + fmaxf(acc[mf][nf][2] + bb0, 0.f);
            s1[nf] += fmaxf(acc[mf][nf][1] + bb1, 0.f)
                    + fmaxf(acc[mf][nf][3] + bb1, 0.f);
        }
    const int grp = (row0 + m0) >> 6;
    #pragma unroll
    for (int nf = 0; nf < 4; ++nf) {
        float a0 = s0[nf], a1 = s1[nf];
        a0 += __shfl_xor_sync(~0u, a0, 4);  a1 += __shfl_xor_sync(~0u, a1, 4);
        a0 += __shfl_xor_sync(~0u, a0, 8);  a1 += __shfl_xor_sync(~0u, a1, 8);
        a0 += __shfl_xor_sync(~0u, a0, 16); a1 += __shfl_xor_sync(~0u, a1, 16);
        if (lane < 4) {
            float2 o2 = {a0 * (1.f/64.f), a1 * (1.f/64.f)};
            *reinterpret_cast<float2*>(&outp[grp * Hc + n0 + nf * 8 + 2 * lane]) = o2;
        }
    }
}

// ---------------------------------------------------------------------------
// K1: weight prep (blocks 0..6) + stage1 (blocks 7..38)  — verbatim R15
// ---------------------------------------------------------------------------
__global__ __launch_bounds__(256, 1)
void k1_prep_stage1(const float* W0, const float* W1, const float* W2,
                    const float* W3, const float* W4, const float* W5,
                    const float* Wn,
                    __nv_bfloat16* oh, __nv_bfloat16* ol,
                    const float* __restrict__ uf,
                    const float* __restrict__ W_ue, const float* __restrict__ b_ue,
                    const float* __restrict__ W_t,  const float* __restrict__ b_t,
                    float* __restrict__ hu, float* __restrict__ hag)
{
    extern __shared__ char smraw[];
    const int tid = threadIdx.x;

    if (blockIdx.x < 7) {
        float* st = reinterpret_cast<float*>(smraw);
        const int m = blockIdx.x;
        uint32_t* ph = reinterpret_cast<uint32_t*>(oh + (size_t)m * Hc * Hc);
        uint32_t* pl = reinterpret_cast<uint32_t*>(ol + (size_t)m * Hc * Hc);

        if (m < 6) {
            const float* Ws[6] = {W0, W1, W2, W3, W4, W5};
            const float* W = Ws[m];
            for (int i = tid; i < Hc * 32; i += 256) {
                const int kr = i >> 5, c4 = i & 31;
                *reinterpret_cast<float4*>(&st[kr * 132 + c4 * 4]) =
                    reinterpret_cast<const float4*>(W)[i];
            }
            __syncthreads();
            for (int i = tid; i < Hc * 64; i += 256) {
                const int n = i >> 6, k2 = (i & 63) * 2;
                const float a = st[k2 * 132 + n];
                const float b = st[(k2 + 1) * 132 + n];
                uint32_t hi, lo;
                split2(a, b, hi, lo);
                ph[n * 64 + (i & 63)] = hi;
                pl[n * 64 + (i & 63)] = lo;
            }
        } else {
            for (int i = tid; i < Hc * 8; i += 256) {
                const int kr = i >> 3, c4 = i & 7;
                *reinterpret_cast<float4*>(&st[kr * 36 + c4 * 4]) =
                    reinterpret_cast<const float4*>(Wn)[i];
            }
            __syncthreads();
            for (int i = tid; i < 64 * 64; i += 256) {
                const int rowp = i >> 6, k = (i & 63) * 2;
                uint32_t hi = 0, lo = 0;
                if (rowp < 32) {
                    const int n = (rowp & 1) * 16 + (rowp >> 1);
                    split2(st[k * 36 + n], st[(k + 1) * 36 + n], hi, lo);
                }
                ph[rowp * 64 + (i & 63)] = hi;
                pl[rowp * 64 + (i & 63)] = lo;
            }
        }
        return;
    }

    float* sA    = reinterpret_cast<float*>(smraw);            // [128][36]
    float* sW    = reinterpret_cast<float*>(smraw + 18432);    // W_ue [32][128]
    float* smean = reinterpret_cast<float*>(smraw + 65536);    // [8][132]
    float* sWt   = reinterpret_cast<float*>(smraw);            // phase2: W_t [128][128]

    const int row0 = (blockIdx.x - 7) * 128;

    for (int i = tid; i < 1024; i += 256) {
        const int r = i >> 3, k4 = i & 7;
        *reinterpret_cast<float4*>(&sA[r * 36 + k4 * 4]) =
            reinterpret_cast<const float4*>(uf)[(size_t)row0 * 8 + i];
    }
    for (int i = tid; i < 1024; i += 256)
        reinterpret_cast<float4*>(sW)[i] = reinterpret_cast<const float4*>(W_ue)[i];
    __syncthreads();

    const int tx = tid & 31, ty = tid >> 5;
    const float4 b4 = reinterpret_cast<const float4*>(b_ue)[tx];
    float4 msum = {0.f, 0.f, 0.f, 0.f};
    #pragma unroll 4
    for (int i = 0; i < 16; ++i) {
        const int r = ty * 16 + i;
        float4 acc = b4;
        #pragma unroll
        for (int k = 0; k < 32; ++k) {
            const float a = sA[r * 36 + k];
            const float4 w = reinterpret_cast<const float4*>(sW)[k * 32 + tx];
            acc.x += a * w.x; acc.y += a * w.y; acc.z += a * w.z; acc.w += a * w.w;
        }
        acc.x = fmaxf(acc.x, 0.f); acc.y = fmaxf(acc.y, 0.f);
        acc.z = fmaxf(acc.z, 0.f); acc.w = fmaxf(acc.w, 0.f);
        reinterpret_cast<float4*>(hu)[(size_t)(row0 + r) * 32 + tx] = acc;
        msum.x += acc.x; msum.y += acc.y; msum.z += acc.z; msum.w += acc.w;
    }
    {
        float4 mv = {msum.x * 0.0625f, msum.y * 0.0625f,
                     msum.z * 0.0625f, msum.w * 0.0625f};
        *reinterpret_cast<float4*>(&smean[ty * 132 + tx * 4]) = mv;
    }
    __syncthreads();
    for (int i = tid; i < 4096; i += 256)
        reinterpret_cast<float4*>(sWt)[i] = reinterpret_cast<const float4*>(W_t)[i];
    __syncthreads();
    {
        const int col4 = tid & 31, gr = tid >> 5;
        float4 acc = reinterpret_cast<const float4*>(b_t)[col4];
        #pragma unroll 4
        for (int k = 0; k < 128; ++k) {
            const float a = smean[gr * 132 + k];
            const float4 w = reinterpret_cast<const float4*>(sWt)[k * 32 + col4];
            acc.x += a * w.x; acc.y += a * w.y; acc.z += a * w.z; acc.w += a * w.w;
        }
        acc.x = fmaxf(acc.x, 0.f); acc.y = fmaxf(acc.y, 0.f);
        acc.z = fmaxf(acc.z, 0.f); acc.w = fmaxf(acc.w, 0.f);
        reinterpret_cast<float4*>(hag)[(size_t)((blockIdx.x - 7) * 8 + gr) * 32 + col4] = acc;
    }
}

// ---------------------------------------------------------------------------
// K2 (grid 148, one wave) — verbatim R15
// ---------------------------------------------------------------------------
__global__ __launch_bounds__(256, 1)
void k2_mixed(const float* __restrict__ noise, const float* __restrict__ hag,
              const __nv_bfloat16* W3h, const __nv_bfloat16* W3l, const float* b3u,
              float* __restrict__ meanU,
              const __nv_bfloat16* W1h, const __nv_bfloat16* W1l, const float* b1,
              float* __restrict__ ta,
              const float* __restrict__ hu,
              const __nv_bfloat16* W0h, const __nv_bfloat16* W0l, const float* b0,
              float* __restrict__ meanA)
{
    extern __shared__ char sm[];
    const int tid = threadIdx.x;
    const int w = tid >> 5, lane = tid & 31;
    const int rr = lane & 7, quad = lane >> 3;

    if (blockIdx.x < 128) {
        constexpr int TM = 128, TILEA = TM * ASTR;
        char* pAh = sm;
        char* pAl = sm + TILEA;
        char* pBh = sm + 2 * TILEA;
        char* pBl = pBh + 128 * ASTR;
        const int row0 = blockIdx.x * TM;

        load_B<128>(W3h, W3l, pBh, pBl, tid);
        load_split_A<TM, true>(noise, hag, row0, pAh, pAl, tid);
        __syncthreads();

        constexpr int MF = 4;
        const int wm = w >> 2, wn = w & 3;
        const int m0 = wm * 64, n0 = wn * 32;
        const uint32_t a_off = (uint32_t)((m0 + rr + ((quad & 1) << 3)) * ASTR + ((quad & 2) << 3));
        const uint32_t b_off = (uint32_t)((n0 + rr + ((quad >> 1) << 3)) * ASTR + ((quad & 1) << 4));
        const uint32_t aAh = smem_u32(pAh), aAl = smem_u32(pAl);
        const uint32_t aBh = smem_u32(pBh), aBl = smem_u32(pBl);

        float acc[MF][4][4];
        // phase0: aggr_u -> meanU
        zero4<MF>(acc);
        mma_3p<MF, 4>(aAh, aAl, aBh, aBl, a_off, b_off, acc);
        __syncthreads();                 // B reads done before overwrite
        epi_mean64(acc, b3u, meanU, row0, m0, n0, lane);
        load_B<128>(W1h, W1l, pBh, pBl, tid);
        __syncthreads();

        // phase1: self_a -> raw store t_a
        zero4<MF>(acc);
        mma_3p<MF, 4>(aAh, aAl, aBh, aBl, a_off, b_off, acc);
        epi_store<MF>(acc, b1, ta, row0, m0, n0, lane);
        return;
    }

    // ---- aggr16 loop (TM=64) ----
    {
        constexpr int TM = 64, TILEA = TM * ASTR;
        char* pAh = sm;
        char* pAl = sm + TILEA;
        char* pBh = sm + 2 * TILEA;
        char* pBl = pBh + 128 * ASTR;

        load_B<128>(W0h, W0l, pBh, pBl, tid);

        constexpr int MF = 2;
        const int wm = w >> 2, wn = w & 3;
        const int m0 = wm * 32, n0 = wn * 32;
        const uint32_t a_off = (uint32_t)((m0 + rr + ((quad & 1) << 3)) * ASTR + ((quad & 2) << 3));
        const uint32_t b_off = (uint32_t)((n0 + rr + ((quad >> 1) << 3)) * ASTR + ((quad & 1) << 4));
        const uint32_t aAh = smem_u32(pAh), aAl = smem_u32(pAl);
        const uint32_t aBh = smem_u32(pBh), aBl = smem_u32(pBl);

        for (int tile = (int)blockIdx.x - 128; tile < NUSER / 64; tile += 20) {
            const int row0 = tile * 64;
            load_split_A<TM, false>(hu, nullptr, row0, pAh, pAl, tid);
            __syncthreads();
            float acc[MF][4][4];
            zero4<MF>(acc);
            mma_3p<MF, 4>(aAh, aAl, aBh, aBl, a_off, b_off, acc);
            epi_mean16<MF>(acc, b0, meanA, row0, m0, n0, lane);
            __syncthreads();             // A reads done before next overwrite
        }
    }
}

// ---------------------------------------------------------------------------
// K3 (grid 64 + 256 = 320):
//  blocks [0,64): user triple (TM=64, verbatim R15)
//  blocks [64,320): comb+self chain (TM=64):
//     A = t_a + meanA[g64]; phase0: mma(W_comb_a) -> epi_resplit(b2) [= ha2 in smem]
//     phase1: mma(W_self_a) -> store t2 = relu(.+b1) raw
// ---------------------------------------------------------------------------
__global__ __launch_bounds__(256, 1)
void k3_mixed(const float* __restrict__ hu,
              const __nv_bfloat16* W4h, const __nv_bfloat16* W4l, const float* b4,
              const float* __restrict__ meanU,
              const __nv_bfloat16* W5h, const __nv_bfloat16* W5l, const float* b5,
              const __nv_bfloat16* W0h, const __nv_bfloat16* W0l, const float* b0,
              float* __restrict__ meanA2,
              const float* __restrict__ ta, const float* __restrict__ meanA,
              const __nv_bfloat16* W2h, const __nv_bfloat16* W2l, const float* b2,
              const __nv_bfloat16* W1h, const __nv_bfloat16* W1l, const float* b1,
              float* __restrict__ t2)
{
    extern __shared__ char sm[];
    const int tid = threadIdx.x;
    const int w = tid >> 5, lane = tid & 31;
    const int rr = lane & 7, quad = lane >> 3;

    constexpr int TM = 64, TILEA = TM * ASTR;
    char* pAh = sm;
    char* pAl = sm + TILEA;
    char* pBh = sm + 2 * TILEA;
    char* pBl = pBh + 128 * ASTR;

    constexpr int MF = 2;
    const int wm = w >> 2, wn = w & 3;
    const int m0 = wm * 32, n0 = wn * 32;
    const uint32_t a_off = (uint32_t)((m0 + rr + ((quad & 1) << 3)) * ASTR + ((quad & 2) << 3));
    const uint32_t b_off = (uint32_t)((n0 + rr + ((quad >> 1) << 3)) * ASTR + ((quad & 1) << 4));
    const uint32_t aAh = smem_u32(pAh), aAl = smem_u32(pAl);
    const uint32_t aBh = smem_u32(pBh), aBl = smem_u32(pBl);

    if (blockIdx.x < 64) {
        const int row0 = blockIdx.x * TM;

        load_B<128>(W4h, W4l, pBh, pBl, tid);
        load_split_A<TM, false>(hu, nullptr, row0, pAh, pAl, tid);
        __syncthreads();

        float acc[MF][4][4];
        // phase0: self_u
        zero4<MF>(acc);
        mma_3p<MF, 4>(aAh, aAl, aBh, aBl, a_off, b_off, acc);
        __syncthreads();
        epi_resplit<MF, true, 4>(acc, b4, meanU, pAh, pAl, row0, m0, n0, lane);
        load_B<128>(W5h, W5l, pBh, pBl, tid);
        __syncthreads();

        // phase1: comb_u
        zero4<MF>(acc);
        mma_3p<MF, 4>(aAh, aAl, aBh, aBl, a_off, b_off, acc);
        __syncthreads();
        epi_resplit<MF, false, 0>(acc, b5, nullptr, pAh, pAl, row0, m0, n0, lane);
        load_B<128>(W0h, W0l, pBh, pBl, tid);
        __syncthreads();

        // phase2: aggr_a -> meanA2
        zero4<MF>(acc);
        mma_3p<MF, 4>(aAh, aAl, aBh, aBl, a_off, b_off, acc);
        epi_mean16<MF>(acc, b0, meanA2, row0, m0, n0, lane);
        return;
    }

    // ---- comb+self chain (TM=64) ----
    {
        const int row0 = ((int)blockIdx.x - 64) * TM;

        load_B<128>(W2h, W2l, pBh, pBl, tid);
        load_split_A<TM, true>(ta, meanA, row0, pAh, pAl, tid);
        __syncthreads();

        float acc[MF][4][4];
        // phase0: comb_a -> ha2 (re-split in smem)
        zero4<MF>(acc);
        mma_3p<MF, 4>(aAh, aAl, aBh, aBl, a_off, b_off, acc);
        __syncthreads();
        epi_resplit<MF, false, 0>(acc, b2, nullptr, pAh, pAl, row0, m0, n0, lane);
        load_B<128>(W1h, W1l, pBh, pBl, tid);
        __syncthreads();

        // phase1: self_a(ha2) -> store t2 raw
        zero4<MF>(acc);
        mma_3p<MF, 4>(aAh, aAl, aBh, aBl, a_off, b_off, acc);
        epi_store<MF>(acc, b1, t2, row0, m0, n0, lane);
    }
}

// ---------------------------------------------------------------------------
// K4 (TM=128, grid 128): A = t2 + meanA2[g64];
//   phase0: mma(W_comb_a) -> epi_resplit(b2); phase1: mma(W_norm') -> normalize -> out
// ---------------------------------------------------------------------------
__global__ __launch_bounds__(256, 1)
void k4_final(const float* __restrict__ t2, const float* __restrict__ meanA2,
              const __nv_bfloat16* __restrict__ W2h, const __nv_bfloat16* __restrict__ W2l,
              const float* __restrict__ b2,
              const __nv_bfloat16* __restrict__ W3h, const __nv_bfloat16* __restrict__ W3l,
              const float* __restrict__ b3,
              float* __restrict__ outp)
{
    extern __shared__ char sm[];
    constexpr int TM = 128, TILEA = TM * ASTR;
    char* pAh = sm;
    char* pAl = sm + TILEA;
    char* pBh = sm + 2 * TILEA;
    char* pBl = pBh + 128 * ASTR;

    const int tid = threadIdx.x;
    const int row0 = blockIdx.x * TM;

    load_B<128>(W2h, W2l, pBh, pBl, tid);
    load_split_A<TM, true>(t2, meanA2, row0, pAh, pAl, tid);
    __syncthreads();

    constexpr int MF = 4;
    const int w = tid >> 5, lane = tid & 31;
    const int wm = w >> 2, wn = w & 3;
    const int m0 = wm * 64, n0 = wn * 32;
    const int rr = lane & 7, quad = lane >> 3;
    const uint32_t a_off = (uint32_t)((m0 + rr + ((quad & 1) << 3)) * ASTR + ((quad & 2) << 3));
    const uint32_t b_off = (uint32_t)((n0 + rr + ((quad >> 1) << 3)) * ASTR + ((quad & 1) << 4));

    const uint32_t aAh = smem_u32(pAh), aAl = smem_u32(pAl);
    const uint32_t aBh = smem_u32(pBh), aBl = smem_u32(pBl);

    float acc[MF][4][4];
    // phase0: comb_a
    zero4<MF>(acc);
    mma_3p<MF, 4>(aAh, aAl, aBh, aBl, a_off, b_off, acc);
    __syncthreads();

    const int tq = lane & 3, gq = lane >> 2;
    epi_resplit<MF, false, 0>(acc, b2, nullptr, pAh, pAl, row0, m0, n0, lane);
    load_B<64>(W3h, W3l, pBh, pBl, tid);     // W_norm' (64 rows)
    __syncthreads();

    // phase1: N = 64 (padded; real cols 0..31 = interleaved re/im pairs)
    const int n03 = wn * 16;
    const uint32_t b_off3 = (uint32_t)((n03 + rr + ((quad >> 1) << 3)) * ASTR + ((quad & 1) << 4));
    float acc3[MF][2][4];
    #pragma unroll
    for (int mf = 0; mf < MF; ++mf)
        #pragma unroll
        for (int nf = 0; nf < 2; ++nf)
            acc3[mf][nf][0] = acc3[mf][nf][1] = acc3[mf][nf][2] = acc3[mf][nf][3] = 0.f;
    mma_3p<MF, 2>(aAh, aAl, aBh, aBl, a_off, b_off3, acc3);

    if (wn < 2) {
        #pragma unroll
        for (int mf = 0; mf < MF; ++mf) {
            const int row = row0 + m0 + mf * 16 + gq;
            #pragma unroll
            for (int nf = 0; nf < 2; ++nf) {
                const int c = n03 + nf * 8 + 2 * tq;     // even; rf = c/2
                const int rf = c >> 1;
                const float br = b3[rf], bi = b3[rf + NRFc];
                {
                    const float re = acc3[mf][nf][0] + br;
                    const float im = acc3[mf][nf][1] + bi;
                    const float inv = rsqrtf(re * re + im * im);
                    float2 o = {re * inv, im * inv};
                    *reinterpret_cast<float2*>(&outp[(size_t)row * 32 + c]) = o;
                }
                {
                    const float re = acc3[mf][nf][2] + br;
                    const float im = acc3[mf][nf][3] + bi;
                    const float inv = rsqrtf(re * re + im * im);
                    float2 o = {re * inv, im * inv};
                    *reinterpret_cast<float2*>(&outp[(size_t)(row + 8) * 32 + c]) = o;
                }
            }
        }
    }
}

// ---------------------------------------------------------------------------
// Host
// ---------------------------------------------------------------------------
extern "C" void kernel_launch(void* const* d_in, const int* in_sizes, int n_in,
                              void* d_out, int out_size)
{
    (void)in_sizes; (void)n_in; (void)out_size;

    const float* user_feat = (const float*)d_in[0];
    const float* noise     = (const float*)d_in[1];
    const float* W_ue     = (const float*)d_in[6],  *b_ue     = (const float*)d_in[7];
    const float* W_t      = (const float*)d_in[8],  *b_t      = (const float*)d_in[9];
    const float* b_aggr_a = (const float*)d_in[11];
    const float* b_self_a = (const float*)d_in[13];
    const float* b_comb_a = (const float*)d_in[15];
    const float* b_aggr_u = (const float*)d_in[17];
    const float* b_self_u = (const float*)d_in[19];
    const float* b_comb_u = (const float*)d_in[21];
    const float* W_norm   = (const float*)d_in[22], *b_norm   = (const float*)d_in[23];
    float* out = (float*)d_out;

    float *hu, *ta, *t2, *meanA, *meanU, *meanA2, *hag;
    __nv_bfloat16 *wth, *wtl;
    cudaGetSymbolAddress((void**)&hu,     g_hu);
    cudaGetSymbolAddress((void**)&ta,     g_ta);
    cudaGetSymbolAddress((void**)&t2,     g_t2);
    cudaGetSymbolAddress((void**)&meanA,  g_meanA);
    cudaGetSymbolAddress((void**)&meanU,  g_meanU);
    cudaGetSymbolAddress((void**)&meanA2, g_meanA2);
    cudaGetSymbolAddress((void**)&hag,    g_hag);
    cudaGetSymbolAddress((void**)&wth,    g_wt_hi);
    cudaGetSymbolAddress((void**)&wtl,    g_wt_lo);

    constexpr int SM_K1    = 69760;
    constexpr int SM_T64   = (2 * 64 + 2 * 128) * ASTR;       // 104448
    constexpr int SM_T128  = 4 * 128 * ASTR;                  // 139264

    cudaFuncSetAttribute((void*)k1_prep_stage1, cudaFuncAttributeMaxDynamicSharedMemorySize, SM_K1);
    cudaFuncSetAttribute((void*)k2_mixed,       cudaFuncAttributeMaxDynamicSharedMemorySize, SM_T128);
    cudaFuncSetAttribute((void*)k3_mixed,       cudaFuncAttributeMaxDynamicSharedMemorySize, SM_T64);
    cudaFuncSetAttribute((void*)k4_final,       cudaFuncAttributeMaxDynamicSharedMemorySize, SM_T128);

    const __nv_bfloat16 *WH0 = wth + 0*16384, *WL0 = wtl + 0*16384;   // aggr_a
    const __nv_bfloat16 *WH1 = wth + 1*16384, *WL1 = wtl + 1*16384;   // self_a
    const __nv_bfloat16 *WH2 = wth + 2*16384, *WL2 = wtl + 2*16384;   // comb_a
    const __nv_bfloat16 *WH3 = wth + 3*16384, *WL3 = wtl + 3*16384;   // aggr_u
    const __nv_bfloat16 *WH4 = wth + 4*16384, *WL4 = wtl + 4*16384;   // self_u
    const __nv_bfloat16 *WH5 = wth + 5*16384, *WL5 = wtl + 5*16384;   // comb_u
    const __nv_bfloat16 *WH6 = wth + 6*16384, *WL6 = wtl + 6*16384;   // W_norm'

    // 1) weight prep (blocks 0..6) + stage1 (blocks 7..38)
    k1_prep_stage1<<<7 + NUSER/128, 256, SM_K1>>>(
        (const float*)d_in[10], (const float*)d_in[12], (const float*)d_in[14],
        (const float*)d_in[16], (const float*)d_in[18], (const float*)d_in[20],
        W_norm, wth, wtl,
        user_feat, W_ue, b_ue, W_t, b_t, hu, hag);

    // 2) K2: agent {aggr_u -> meanU; self_a -> t_a raw}  ||  aggr16 -> meanA
    k2_mixed<<<148, 256, SM_T128>>>(noise, hag,
                                    WH3, WL3, b_aggr_u, meanU,
                                    WH1, WL1, b_self_a, ta,
                                    hu, WH0, WL0, b_aggr_a, meanA);

    // 3) K3: user triple -> meanA2  ||  comb_a+self_a chain -> t2
    k3_mixed<<<64 + NAG/64, 256, SM_T64>>>(hu,
                                           WH4, WL4, b_self_u, meanU,
                                           WH5, WL5, b_comb_u,
                                           WH0, WL0, b_aggr_a, meanA2,
                                           ta, meanA, WH2, WL2, b_comb_a,
                                           WH1, WL1, b_self_a, t2);

    // 4) K4: comb_a(t2 + meanA2) + norm projection + normalize -> out
    k4_final<<<NAG/128, 256, SM_T128>>>(t2, meanA2, WH2, WL2, b_comb_a,
                                        WH6, WL6, b_norm, out);
}

// round 17
// speedup vs baseline: 1.0400x; 1.0400x over previous
#include <cuda_runtime.h>
#include <cuda_bf16.h>
#include <cstdint>
#include <cstddef>

// ---------------------------------------------------------------------------
// Problem constants
// ---------------------------------------------------------------------------
namespace {
constexpr int Bg    = 256;
constexpr int Hc    = 128;
constexpr int NRFc  = 16;
constexpr int NUSER = 4096;    // Bg*16
constexpr int NAG   = 16384;   // Bg*64
constexpr int APAD  = 136;     // bf16 elems per smem row
constexpr int ASTR  = APAD * 2; // 272 bytes
}

// ---------------------------------------------------------------------------
// Scratch (device globals — no allocation allowed)
// ---------------------------------------------------------------------------
__device__ float g_hu  [NUSER * Hc];
__device__ float g_ta  [NAG   * Hc];   // raw relu((noise+hag)@W_self_a + b1)
__device__ float g_ha2 [NAG   * Hc];
__device__ float g_meanA [Bg * Hc];
__device__ float g_meanU [Bg * Hc];
__device__ float g_meanA2[Bg * Hc];
__device__ float g_hag [Bg * Hc];
// Pre-transposed + hi/lo-split weights: slots 0..5 = H x H, slot 6 = W_norm' (64x128 used)
__device__ __nv_bfloat16 g_wt_hi[7 * Hc * Hc];
__device__ __nv_bfloat16 g_wt_lo[7 * Hc * Hc];

// ---------------------------------------------------------------------------
// Helpers
// ---------------------------------------------------------------------------
__device__ __forceinline__ uint32_t smem_u32(const void* p) {
    uint32_t a;
    asm("{ .reg .u64 t; cvta.to.shared.u64 t, %1; cvt.u32.u64 %0, t; }"
        : "=r"(a) : "l"(p));
    return a;
}
__device__ __forceinline__ void ldsm4(uint32_t* r, uint32_t addr) {
    asm volatile("ldmatrix.sync.aligned.m8n8.x4.shared.b16 {%0,%1,%2,%3}, [%4];"
                 : "=r"(r[0]), "=r"(r[1]), "=r"(r[2]), "=r"(r[3]) : "r"(addr));
}
__device__ __forceinline__ void mma16816(float* d, const uint32_t* a, const uint32_t* b) {
    asm volatile(
        "mma.sync.aligned.m16n8k16.row.col.f32.bf16.bf16.f32 "
        "{%0,%1,%2,%3}, {%4,%5,%6,%7}, {%8,%9}, {%0,%1,%2,%3};"
        : "+f"(d[0]), "+f"(d[1]), "+f"(d[2]), "+f"(d[3])
        : "r"(a[0]), "r"(a[1]), "r"(a[2]), "r"(a[3]), "r"(b[0]), "r"(b[1]));
}
__device__ __forceinline__ uint32_t pack_bf2(__nv_bfloat16 a, __nv_bfloat16 b) {
    return (uint32_t)__bfloat16_as_ushort(a) | ((uint32_t)__bfloat16_as_ushort(b) << 16);
}
__device__ __forceinline__ void split2(float a, float b, uint32_t& hi, uint32_t& lo) {
    const __nv_bfloat16 h0 = __float2bfloat16(a), h1 = __float2bfloat16(b);
    hi = pack_bf2(h0, h1);
    lo = pack_bf2(__float2bfloat16(a - __bfloat162float(h0)),
                  __float2bfloat16(b - __bfloat162float(h1)));
}

// A tile load: fp32 (+optional broadcast add, group = row>>6), hi/lo split to smem
template<int TM, bool ADD>
__device__ __forceinline__ void load_split_A(const float* __restrict__ A,
                                             const float* __restrict__ addv,
                                             int row0, char* pAh, char* pAl, int tid)
{
    #pragma unroll
    for (int i = tid; i < TM * 16; i += 256) {
        const int r = i >> 4, k = (i & 15) * 8;
        const float* ap = A + (size_t)(row0 + r) * Hc + k;
        float v[8];
        *reinterpret_cast<float4*>(&v[0]) = *reinterpret_cast<const float4*>(ap);
        *reinterpret_cast<float4*>(&v[4]) = *reinterpret_cast<const float4*>(ap + 4);
        if (ADD) {
            const float* mp = addv + ((row0 + r) >> 6) * Hc + k;
            float m[8];
            *reinterpret_cast<float4*>(&m[0]) = *reinterpret_cast<const float4*>(mp);
            *reinterpret_cast<float4*>(&m[4]) = *reinterpret_cast<const float4*>(mp + 4);
            #pragma unroll
            for (int j = 0; j < 8; ++j) v[j] += m[j];
        }
        uint32_t hb[4], lb[4];
        #pragma unroll
        for (int j = 0; j < 4; ++j) split2(v[2*j], v[2*j+1], hb[j], lb[j]);
        const uint32_t o = (uint32_t)(r * ASTR + (i & 15) * 16);
        *reinterpret_cast<uint4*>(pAh + o) = *reinterpret_cast<uint4*>(hb);
        *reinterpret_cast<uint4*>(pAl + o) = *reinterpret_cast<uint4*>(lb);
    }
}

template<int NROWS>
__device__ __forceinline__ void load_B(const __nv_bfloat16* __restrict__ Wh,
                                       const __nv_bfloat16* __restrict__ Wl,
                                       char* pBh, char* pBl, int tid)
{
    const uint4* wh = reinterpret_cast<const uint4*>(Wh);
    const uint4* wl = reinterpret_cast<const uint4*>(Wl);
    #pragma unroll
    for (int i = tid; i < NROWS * 16; i += 256) {
        const uint32_t o = (uint32_t)((i >> 4) * ASTR + (i & 15) * 16);
        *reinterpret_cast<uint4*>(pBh + o) = wh[i];
        *reinterpret_cast<uint4*>(pBl + o) = wl[i];
    }
}

// 3-pass hi/lo MMA over K=128
template<int MF, int NF>
__device__ __forceinline__ void mma_3p(uint32_t aAh, uint32_t aAl,
                                       uint32_t aBh, uint32_t aBl,
                                       uint32_t a_off, uint32_t b_off,
                                       float (*acc)[NF][4])
{
    #pragma unroll
    for (int pass = 0; pass < 3; ++pass) {
        const uint32_t Ab = (pass == 2 ? aAl : aAh) + a_off;
        const uint32_t Bb = (pass == 1 ? aBl : aBh) + b_off;
        #pragma unroll
        for (int kc = 0; kc < 8; ++kc) {
            const uint32_t kb = (uint32_t)kc * 32;
            uint32_t af[MF][4];
            #pragma unroll
            for (int mf = 0; mf < MF; ++mf)
                ldsm4(af[mf], Ab + (uint32_t)(mf * 16 * ASTR) + kb);
            uint32_t bfr[NF][2];
            #pragma unroll
            for (int p = 0; p < NF / 2; ++p) {
                uint32_t t[4];
                ldsm4(t, Bb + (uint32_t)(p * 16 * ASTR) + kb);
                bfr[2*p][0] = t[0]; bfr[2*p][1] = t[1];
                bfr[2*p+1][0] = t[2]; bfr[2*p+1][1] = t[3];
            }
            #pragma unroll
            for (int mf = 0; mf < MF; ++mf)
                #pragma unroll
                for (int nf = 0; nf < NF; ++nf)
                    mma16816(acc[mf][nf], af[mf], bfr[nf]);
        }
    }
}
template<int MF>
__device__ __forceinline__ void zero4(float (*acc)[4][4]) {
    #pragma unroll
    for (int mf = 0; mf < MF; ++mf)
        #pragma unroll
        for (int nf = 0; nf < 4; ++nf)
            acc[mf][nf][0] = acc[mf][nf][1] = acc[mf][nf][2] = acc[mf][nf][3] = 0.f;
}

// epilogue: e = relu(acc+b) (+mean[g]) re-split into A tiles
template<int MF, bool ADDMEAN, int SHIFT>
__device__ __forceinline__ void epi_resplit(float (*acc)[4][4],
                                            const float* __restrict__ bias,
                                            const float* __restrict__ meanv,
                                            char* pAh, char* pAl,
                                            int row0, int m0, int n0, int lane)
{
    const int tq = lane & 3, gq = lane >> 2;
    #pragma unroll
    for (int mf = 0; mf < MF; ++mf) {
        const int r0 = m0 + mf * 16 + gq;
        const int g = ADDMEAN ? ((SHIFT == 6) ? ((row0 + m0) >> 6)
                                              : ((row0 + m0 + mf * 16) >> 4)) : 0;
        #pragma unroll
        for (int nf = 0; nf < 4; ++nf) {
            const int c = n0 + nf * 8 + 2 * tq;
            float mx = 0.f, my = 0.f;
            if (ADDMEAN) {
                const float2 mv = *reinterpret_cast<const float2*>(&meanv[g * Hc + c]);
                mx = mv.x; my = mv.y;
            }
            const float bb0 = bias[c], bb1 = bias[c + 1];
            const float e0 = fmaxf(acc[mf][nf][0] + bb0, 0.f) + mx;
            const float e1 = fmaxf(acc[mf][nf][1] + bb1, 0.f) + my;
            const float e2 = fmaxf(acc[mf][nf][2] + bb0, 0.f) + mx;
            const float e3 = fmaxf(acc[mf][nf][3] + bb1, 0.f) + my;
            uint32_t hi0, lo0, hi1, lo1;
            split2(e0, e1, hi0, lo0);
            split2(e2, e3, hi1, lo1);
            *reinterpret_cast<uint32_t*>(pAh + r0 * ASTR + c * 2) = hi0;
            *reinterpret_cast<uint32_t*>(pAl + r0 * ASTR + c * 2) = lo0;
            *reinterpret_cast<uint32_t*>(pAh + (r0 + 8) * ASTR + c * 2) = hi1;
            *reinterpret_cast<uint32_t*>(pAl + (r0 + 8) * ASTR + c * 2) = lo1;
        }
    }
}

// full-store epilogue: out[row][c] = relu(acc + b)
template<int MF>
__device__ __forceinline__ void epi_store(float (*acc)[4][4],
                                          const float* __restrict__ bias,
                                          float* __restrict__ outp,
                                          int row0, int m0, int n0, int lane)
{
    const int tq = lane & 3, gq = lane >> 2;
    #pragma unroll
    for (int mf = 0; mf < MF; ++mf) {
        const int row = row0 + m0 + mf * 16 + gq;
        #pragma unroll
        for (int nf = 0; nf < 4; ++nf) {
            const int c = n0 + nf * 8 + 2 * tq;
            const float bb0 = bias[c], bb1 = bias[c + 1];
            float2 lo, hi;
            lo.x = fmaxf(acc[mf][nf][0] + bb0, 0.f);
            lo.y = fmaxf(acc[mf][nf][1] + bb1, 0.f);
            hi.x = fmaxf(acc[mf][nf][2] + bb0, 0.f);
            hi.y = fmaxf(acc[mf][nf][3] + bb1, 0.f);
            *reinterpret_cast<float2*>(&outp[(size_t)row * Hc + c]) = lo;
            *reinterpret_cast<float2*>(&outp[(size_t)(row + 8) * Hc + c]) = hi;
        }
    }
}

// mean-16 epilogue
template<int MF>
__device__ __forceinline__ void epi_mean16(float (*acc)[4][4],
                                           const float* __restrict__ bias,
                                           float* __restrict__ outp,
                                           int row0, int m0, int n0, int lane)
{
    const int tq = lane & 3;
    #pragma unroll
    for (int mf = 0; mf < MF; ++mf) {
        const int grp = (row0 + m0 + mf * 16) >> 4;
        #pragma unroll
        for (int nf = 0; nf < 4; ++nf) {
            const int c = n0 + nf * 8 + 2 * tq;
            const float bb0 = bias[c], bb1 = bias[c + 1];
            float s0 = fmaxf(acc[mf][nf][0] + bb0, 0.f)
                     + fmaxf(acc[mf][nf][2] + bb0, 0.f);
            float s1 = fmaxf(acc[mf][nf][1] + bb1, 0.f)
                     + fmaxf(acc[mf][nf][3] + bb1, 0.f);
            s0 += __shfl_xor_sync(~0u, s0, 4);  s1 += __shfl_xor_sync(~0u, s1, 4);
            s0 += __shfl_xor_sync(~0u, s0, 8);  s1 += __shfl_xor_sync(~0u, s1, 8);
            s0 += __shfl_xor_sync(~0u, s0, 16); s1 += __shfl_xor_sync(~0u, s1, 16);
            if (lane < 4) {
                float2 o2 = {s0 * 0.0625f, s1 * 0.0625f};
                *reinterpret_cast<float2*>(&outp[grp * Hc + n0 + nf * 8 + 2 * lane]) = o2;
            }
        }
    }
}

// mean-64 epilogue (MF=4)
__device__ __forceinline__ void epi_mean64(float (*acc)[4][4],
                                           const float* __restrict__ bias,
                                           float* __restrict__ outp,
                                           int row0, int m0, int n0, int lane)
{
    const int tq = lane & 3;
    float s0[4] = {0,0,0,0}, s1[4] = {0,0,0,0};
    #pragma unroll
    for (int mf = 0; mf < 4; ++mf)
        #pragma unroll
        for (int nf = 0; nf < 4; ++nf) {
            const float bb0 = bias[n0 + nf * 8 + 2 * tq];
            const float bb1 = bias[n0 + nf * 8 + 2 * tq + 1];
            s0[nf] += fmaxf(acc[mf][nf][0] + bb0, 0.f)
                    + fmaxf(acc[mf][nf][2] + bb0, 0.f);
            s1[nf] += fmaxf(acc[mf][nf][1] + bb1, 0.f)
                    + fmaxf(acc[mf][nf][3] + bb1, 0.f);
        }
    const int grp = (row0 + m0) >> 6;
    #pragma unroll
    for (int nf = 0; nf < 4; ++nf) {
        float a0 = s0[nf], a1 = s1[nf];
        a0 += __shfl_xor_sync(~0u, a0, 4);  a1 += __shfl_xor_sync(~0u, a1, 4);
        a0 += __shfl_xor_sync(~0u, a0, 8);  a1 += __shfl_xor_sync(~0u, a1, 8);
        a0 += __shfl_xor_sync(~0u, a0, 16); a1 += __shfl_xor_sync(~0u, a1, 16);
        if (lane < 4) {
            float2 o2 = {a0 * (1.f/64.f), a1 * (1.f/64.f)};
            *reinterpret_cast<float2*>(&outp[grp * Hc + n0 + nf * 8 + 2 * lane]) = o2;
        }
    }
}

// ---------------------------------------------------------------------------
// K1: weight prep (blocks 0..6) + stage1 (blocks 7..38)
// ---------------------------------------------------------------------------
__global__ __launch_bounds__(256, 1)
void k1_prep_stage1(const float* W0, const float* W1, const float* W2,
                    const float* W3, const float* W4, const float* W5,
                    const float* Wn,
                    __nv_bfloat16* oh, __nv_bfloat16* ol,
                    const float* __restrict__ uf,
                    const float* __restrict__ W_ue, const float* __restrict__ b_ue,
                    const float* __restrict__ W_t,  const float* __restrict__ b_t,
                    float* __restrict__ hu, float* __restrict__ hag)
{
    extern __shared__ char smraw[];
    const int tid = threadIdx.x;

    if (blockIdx.x < 7) {
        float* st = reinterpret_cast<float*>(smraw);
        const int m = blockIdx.x;
        uint32_t* ph = reinterpret_cast<uint32_t*>(oh + (size_t)m * Hc * Hc);
        uint32_t* pl = reinterpret_cast<uint32_t*>(ol + (size_t)m * Hc * Hc);

        if (m < 6) {
            const float* Ws[6] = {W0, W1, W2, W3, W4, W5};
            const float* W = Ws[m];
            for (int i = tid; i < Hc * 32; i += 256) {
                const int kr = i >> 5, c4 = i & 31;
                *reinterpret_cast<float4*>(&st[kr * 132 + c4 * 4]) =
                    reinterpret_cast<const float4*>(W)[i];
            }
            __syncthreads();
            for (int i = tid; i < Hc * 64; i += 256) {
                const int n = i >> 6, k2 = (i & 63) * 2;
                const float a = st[k2 * 132 + n];
                const float b = st[(k2 + 1) * 132 + n];
                uint32_t hi, lo;
                split2(a, b, hi, lo);
                ph[n * 64 + (i & 63)] = hi;
                pl[n * 64 + (i & 63)] = lo;
            }
        } else {
            for (int i = tid; i < Hc * 8; i += 256) {
                const int kr = i >> 3, c4 = i & 7;
                *reinterpret_cast<float4*>(&st[kr * 36 + c4 * 4]) =
                    reinterpret_cast<const float4*>(Wn)[i];
            }
            __syncthreads();
            for (int i = tid; i < 64 * 64; i += 256) {
                const int rowp = i >> 6, k = (i & 63) * 2;
                uint32_t hi = 0, lo = 0;
                if (rowp < 32) {
                    const int n = (rowp & 1) * 16 + (rowp >> 1);
                    split2(st[k * 36 + n], st[(k + 1) * 36 + n], hi, lo);
                }
                ph[rowp * 64 + (i & 63)] = hi;
                pl[rowp * 64 + (i & 63)] = lo;
            }
        }
        return;
    }

    float* sA    = reinterpret_cast<float*>(smraw);            // [128][36]
    float* sW    = reinterpret_cast<float*>(smraw + 18432);    // W_ue [32][128]
    float* smean = reinterpret_cast<float*>(smraw + 65536);    // [8][132]
    float* sWt   = reinterpret_cast<float*>(smraw);            // phase2: W_t [128][128]

    const int row0 = (blockIdx.x - 7) * 128;

    for (int i = tid; i < 1024; i += 256) {
        const int r = i >> 3, k4 = i & 7;
        *reinterpret_cast<float4*>(&sA[r * 36 + k4 * 4]) =
            reinterpret_cast<const float4*>(uf)[(size_t)row0 * 8 + i];
    }
    for (int i = tid; i < 1024; i += 256)
        reinterpret_cast<float4*>(sW)[i] = reinterpret_cast<const float4*>(W_ue)[i];
    __syncthreads();

    const int tx = tid & 31, ty = tid >> 5;
    const float4 b4 = reinterpret_cast<const float4*>(b_ue)[tx];
    float4 msum = {0.f, 0.f, 0.f, 0.f};
    #pragma unroll 4
    for (int i = 0; i < 16; ++i) {
        const int r = ty * 16 + i;
        float4 acc = b4;
        #pragma unroll
        for (int k = 0; k < 32; ++k) {
            const float a = sA[r * 36 + k];
            const float4 w = reinterpret_cast<const float4*>(sW)[k * 32 + tx];
            acc.x += a * w.x; acc.y += a * w.y; acc.z += a * w.z; acc.w += a * w.w;
        }
        acc.x = fmaxf(acc.x, 0.f); acc.y = fmaxf(acc.y, 0.f);
        acc.z = fmaxf(acc.z, 0.f); acc.w = fmaxf(acc.w, 0.f);
        reinterpret_cast<float4*>(hu)[(size_t)(row0 + r) * 32 + tx] = acc;
        msum.x += acc.x; msum.y += acc.y; msum.z += acc.z; msum.w += acc.w;
    }
    {
        float4 mv = {msum.x * 0.0625f, msum.y * 0.0625f,
                     msum.z * 0.0625f, msum.w * 0.0625f};
        *reinterpret_cast<float4*>(&smean[ty * 132 + tx * 4]) = mv;
    }
    __syncthreads();
    for (int i = tid; i < 4096; i += 256)
        reinterpret_cast<float4*>(sWt)[i] = reinterpret_cast<const float4*>(W_t)[i];
    __syncthreads();
    {
        const int col4 = tid & 31, gr = tid >> 5;
        float4 acc = reinterpret_cast<const float4*>(b_t)[col4];
        #pragma unroll 4
        for (int k = 0; k < 128; ++k) {
            const float a = smean[gr * 132 + k];
            const float4 w = reinterpret_cast<const float4*>(sWt)[k * 32 + col4];
            acc.x += a * w.x; acc.y += a * w.y; acc.z += a * w.z; acc.w += a * w.w;
        }
        acc.x = fmaxf(acc.x, 0.f); acc.y = fmaxf(acc.y, 0.f);
        acc.z = fmaxf(acc.z, 0.f); acc.w = fmaxf(acc.w, 0.f);
        reinterpret_cast<float4*>(hag)[(size_t)((blockIdx.x - 7) * 8 + gr) * 32 + col4] = acc;
    }
}

// ---------------------------------------------------------------------------
// K2 (grid 148, one wave):
//  blocks [0,128): TM=128 agent pair, one shared A tile (noise+hag):
//     phase0: mma(W_aggr_u) -> mean64 -> meanU
//     phase1: mma(W_self_a) -> raw store t_a = relu(.+b1)
//  blocks [128,148): loop over aggr16 tiles (TM=64): meanA = mean16(relu(hu@W0+b0))
// ---------------------------------------------------------------------------
__global__ __launch_bounds__(256, 1)
void k2_mixed(const float* __restrict__ noise, const float* __restrict__ hag,
              const __nv_bfloat16* W3h, const __nv_bfloat16* W3l, const float* b3u,
              float* __restrict__ meanU,
              const __nv_bfloat16* W1h, const __nv_bfloat16* W1l, const float* b1,
              float* __restrict__ ta,
              const float* __restrict__ hu,
              const __nv_bfloat16* W0h, const __nv_bfloat16* W0l, const float* b0,
              float* __restrict__ meanA)
{
    extern __shared__ char sm[];
    const int tid = threadIdx.x;
    const int w = tid >> 5, lane = tid & 31;
    const int rr = lane & 7, quad = lane >> 3;

    if (blockIdx.x < 128) {
        constexpr int TM = 128, TILEA = TM * ASTR;
        char* pAh = sm;
        char* pAl = sm + TILEA;
        char* pBh = sm + 2 * TILEA;
        char* pBl = pBh + 128 * ASTR;
        const int row0 = blockIdx.x * TM;

        load_B<128>(W3h, W3l, pBh, pBl, tid);
        load_split_A<TM, true>(noise, hag, row0, pAh, pAl, tid);
        __syncthreads();

        constexpr int MF = 4;
        const int wm = w >> 2, wn = w & 3;
        const int m0 = wm * 64, n0 = wn * 32;
        const uint32_t a_off = (uint32_t)((m0 + rr + ((quad & 1) << 3)) * ASTR + ((quad & 2) << 3));
        const uint32_t b_off = (uint32_t)((n0 + rr + ((quad >> 1) << 3)) * ASTR + ((quad & 1) << 4));
        const uint32_t aAh = smem_u32(pAh), aAl = smem_u32(pAl);
        const uint32_t aBh = smem_u32(pBh), aBl = smem_u32(pBl);

        float acc[MF][4][4];
        // phase0: aggr_u -> meanU
        zero4<MF>(acc);
        mma_3p<MF, 4>(aAh, aAl, aBh, aBl, a_off, b_off, acc);
        __syncthreads();                 // B reads done before overwrite
        epi_mean64(acc, b3u, meanU, row0, m0, n0, lane);
        load_B<128>(W1h, W1l, pBh, pBl, tid);
        __syncthreads();

        // phase1: self_a -> raw store t_a
        zero4<MF>(acc);
        mma_3p<MF, 4>(aAh, aAl, aBh, aBl, a_off, b_off, acc);
        epi_store<MF>(acc, b1, ta, row0, m0, n0, lane);
        return;
    }

    // ---- aggr16 loop (TM=64) ----
    {
        constexpr int TM = 64, TILEA = TM * ASTR;
        char* pAh = sm;
        char* pAl = sm + TILEA;
        char* pBh = sm + 2 * TILEA;
        char* pBl = pBh + 128 * ASTR;

        load_B<128>(W0h, W0l, pBh, pBl, tid);

        constexpr int MF = 2;
        const int wm = w >> 2, wn = w & 3;
        const int m0 = wm * 32, n0 = wn * 32;
        const uint32_t a_off = (uint32_t)((m0 + rr + ((quad & 1) << 3)) * ASTR + ((quad & 2) << 3));
        const uint32_t b_off = (uint32_t)((n0 + rr + ((quad >> 1) << 3)) * ASTR + ((quad & 1) << 4));
        const uint32_t aAh = smem_u32(pAh), aAl = smem_u32(pAl);
        const uint32_t aBh = smem_u32(pBh), aBl = smem_u32(pBl);

        for (int tile = (int)blockIdx.x - 128; tile < NUSER / 64; tile += 20) {
            const int row0 = tile * 64;
            load_split_A<TM, false>(hu, nullptr, row0, pAh, pAl, tid);
            __syncthreads();
            float acc[MF][4][4];
            zero4<MF>(acc);
            mma_3p<MF, 4>(aAh, aAl, aBh, aBl, a_off, b_off, acc);
            epi_mean16<MF>(acc, b0, meanA, row0, m0, n0, lane);
            __syncthreads();             // A reads done before next overwrite
        }
    }
}

// ---------------------------------------------------------------------------
// K3 (grid 64 + 256 = 320):
//  blocks [0,64): user triple (TM=64):
//     self_u -> epi1(+meanU g16) -> comb_u -> epi2 -> aggr_a -> mean16 -> meanA2
//  blocks [64,320): comb_a (TM=64): ha2 = relu((t_a + meanA[g64]) @ W2 + b2)
// ---------------------------------------------------------------------------
__global__ __launch_bounds__(256, 1)
void k3_mixed(const float* __restrict__ hu,
              const __nv_bfloat16* W4h, const __nv_bfloat16* W4l, const float* b4,
              const float* __restrict__ meanU,
              const __nv_bfloat16* W5h, const __nv_bfloat16* W5l, const float* b5,
              const __nv_bfloat16* W0h, const __nv_bfloat16* W0l, const float* b0,
              float* __restrict__ meanA2,
              const float* __restrict__ ta, const float* __restrict__ meanA,
              const __nv_bfloat16* W2h, const __nv_bfloat16* W2l, const float* b2,
              float* __restrict__ ha2)
{
    extern __shared__ char sm[];
    const int tid = threadIdx.x;
    const int w = tid >> 5, lane = tid & 31;
    const int rr = lane & 7, quad = lane >> 3;

    constexpr int TM = 64, TILEA = TM * ASTR;
    char* pAh = sm;
    char* pAl = sm + TILEA;
    char* pBh = sm + 2 * TILEA;
    char* pBl = pBh + 128 * ASTR;

    constexpr int MF = 2;
    const int wm = w >> 2, wn = w & 3;
    const int m0 = wm * 32, n0 = wn * 32;
    const uint32_t a_off = (uint32_t)((m0 + rr + ((quad & 1) << 3)) * ASTR + ((quad & 2) << 3));
    const uint32_t b_off = (uint32_t)((n0 + rr + ((quad >> 1) << 3)) * ASTR + ((quad & 1) << 4));
    const uint32_t aAh = smem_u32(pAh), aAl = smem_u32(pAl);
    const uint32_t aBh = smem_u32(pBh), aBl = smem_u32(pBl);

    if (blockIdx.x < 64) {
        const int row0 = blockIdx.x * TM;

        load_B<128>(W4h, W4l, pBh, pBl, tid);
        load_split_A<TM, false>(hu, nullptr, row0, pAh, pAl, tid);
        __syncthreads();

        float acc[MF][4][4];
        // phase0: self_u
        zero4<MF>(acc);
        mma_3p<MF, 4>(aAh, aAl, aBh, aBl, a_off, b_off, acc);
        __syncthreads();
        epi_resplit<MF, true, 4>(acc, b4, meanU, pAh, pAl, row0, m0, n0, lane);
        load_B<128>(W5h, W5l, pBh, pBl, tid);
        __syncthreads();

        // phase1: comb_u
        zero4<MF>(acc);
        mma_3p<MF, 4>(aAh, aAl, aBh, aBl, a_off, b_off, acc);
        __syncthreads();
        epi_resplit<MF, false, 0>(acc, b5, nullptr, pAh, pAl, row0, m0, n0, lane);
        load_B<128>(W0h, W0l, pBh, pBl, tid);
        __syncthreads();

        // phase2: aggr_a -> meanA2
        zero4<MF>(acc);
        mma_3p<MF, 4>(aAh, aAl, aBh, aBl, a_off, b_off, acc);
        epi_mean16<MF>(acc, b0, meanA2, row0, m0, n0, lane);
        return;
    }

    // ---- comb_a (TM=64): ha2 = relu((t_a + meanA[g64]) @ W2 + b2) ----
    {
        const int row0 = ((int)blockIdx.x - 64) * TM;

        load_B<128>(W2h, W2l, pBh, pBl, tid);
        load_split_A<TM, true>(ta, meanA, row0, pAh, pAl, tid);
        __syncthreads();

        float acc[MF][4][4];
        zero4<MF>(acc);
        mma_3p<MF, 4>(aAh, aAl, aBh, aBl, a_off, b_off, acc);
        epi_store<MF>(acc, b2, ha2, row0, m0, n0, lane);
    }
}

// ---------------------------------------------------------------------------
// K4: triple fused (conv2 agent + final)
// ---------------------------------------------------------------------------
__global__ __launch_bounds__(256, 1)
void gemm_triple(const float* __restrict__ A,
                 const __nv_bfloat16* __restrict__ W1h, const __nv_bfloat16* __restrict__ W1l,
                 const float* __restrict__ b1,
                 const float* __restrict__ meanv,
                 const __nv_bfloat16* __restrict__ W2h, const __nv_bfloat16* __restrict__ W2l,
                 const float* __restrict__ b2,
                 const __nv_bfloat16* __restrict__ W3h, const __nv_bfloat16* __restrict__ W3l,
                 const float* __restrict__ b3,
                 float* __restrict__ outp)
{
    extern __shared__ char sm[];
    constexpr int TM = 128, TILEA = TM * ASTR;
    char* pAh = sm;
    char* pAl = sm + TILEA;
    char* pBh = sm + 2 * TILEA;
    char* pBl = pBh + 128 * ASTR;

    const int tid = threadIdx.x;
    const int row0 = blockIdx.x * TM;

    load_B<128>(W1h, W1l, pBh, pBl, tid);
    load_split_A<TM, false>(A, nullptr, row0, pAh, pAl, tid);
    __syncthreads();

    constexpr int MF = 4;
    const int w = tid >> 5, lane = tid & 31;
    const int wm = w >> 2, wn = w & 3;
    const int m0 = wm * 64, n0 = wn * 32;
    const int rr = lane & 7, quad = lane >> 3;
    const uint32_t a_off = (uint32_t)((m0 + rr + ((quad & 1) << 3)) * ASTR + ((quad & 2) << 3));
    const uint32_t b_off = (uint32_t)((n0 + rr + ((quad >> 1) << 3)) * ASTR + ((quad & 1) << 4));

    const uint32_t aAh = smem_u32(pAh), aAl = smem_u32(pAl);
    const uint32_t aBh = smem_u32(pBh), aBl = smem_u32(pBl);

    float acc[MF][4][4];
    zero4<MF>(acc);
    mma_3p<MF, 4>(aAh, aAl, aBh, aBl, a_off, b_off, acc);
    __syncthreads();

    const int tq = lane & 3, gq = lane >> 2;
    epi_resplit<MF, true, 6>(acc, b1, meanv, pAh, pAl, row0, m0, n0, lane);
    load_B<128>(W2h, W2l, pBh, pBl, tid);
    __syncthreads();

    zero4<MF>(acc);
    mma_3p<MF, 4>(aAh, aAl, aBh, aBl, a_off, b_off, acc);
    __syncthreads();

    epi_resplit<MF, false, 0>(acc, b2, nullptr, pAh, pAl, row0, m0, n0, lane);
    load_B<64>(W3h, W3l, pBh, pBl, tid);
    __syncthreads();

    // MMA3: N = 64 (padded; real cols 0..31 = interleaved re/im pairs)
    const int n03 = wn * 16;
    const uint32_t b_off3 = (uint32_t)((n03 + rr + ((quad >> 1) << 3)) * ASTR + ((quad & 1) << 4));
    float acc3[MF][2][4];
    #pragma unroll
    for (int mf = 0; mf < MF; ++mf)
        #pragma unroll
        for (int nf = 0; nf < 2; ++nf)
            acc3[mf][nf][0] = acc3[mf][nf][1] = acc3[mf][nf][2] = acc3[mf][nf][3] = 0.f;
    mma_3p<MF, 2>(aAh, aAl, aBh, aBl, a_off, b_off3, acc3);

    if (wn < 2) {
        #pragma unroll
        for (int mf = 0; mf < MF; ++mf) {
            const int row = row0 + m0 + mf * 16 + gq;
            #pragma unroll
            for (int nf = 0; nf < 2; ++nf) {
                const int c = n03 + nf * 8 + 2 * tq;     // even; rf = c/2
                const int rf = c >> 1;
                const float br = b3[rf], bi = b3[rf + NRFc];
                {
                    const float re = acc3[mf][nf][0] + br;
                    const float im = acc3[mf][nf][1] + bi;
                    const float inv = rsqrtf(re * re + im * im);
                    float2 o = {re * inv, im * inv};
                    *reinterpret_cast<float2*>(&outp[(size_t)row * 32 + c]) = o;
                }
                {
                    const float re = acc3[mf][nf][2] + br;
                    const float im = acc3[mf][nf][3] + bi;
                    const float inv = rsqrtf(re * re + im * im);
                    float2 o = {re * inv, im * inv};
                    *reinterpret_cast<float2*>(&outp[(size_t)(row + 8) * 32 + c]) = o;
                }
            }
        }
    }
}

// ---------------------------------------------------------------------------
// Host
// ---------------------------------------------------------------------------
extern "C" void kernel_launch(void* const* d_in, const int* in_sizes, int n_in,
                              void* d_out, int out_size)
{
    (void)in_sizes; (void)n_in; (void)out_size;

    const float* user_feat = (const float*)d_in[0];
    const float* noise     = (const float*)d_in[1];
    const float* W_ue     = (const float*)d_in[6],  *b_ue     = (const float*)d_in[7];
    const float* W_t      = (const float*)d_in[8],  *b_t      = (const float*)d_in[9];
    const float* b_aggr_a = (const float*)d_in[11];
    const float* b_self_a = (const float*)d_in[13];
    const float* b_comb_a = (const float*)d_in[15];
    const float* b_aggr_u = (const float*)d_in[17];
    const float* b_self_u = (const float*)d_in[19];
    const float* b_comb_u = (const float*)d_in[21];
    const float* W_norm   = (const float*)d_in[22], *b_norm   = (const float*)d_in[23];
    float* out = (float*)d_out;

    float *hu, *ta, *ha2, *meanA, *meanU, *meanA2, *hag;
    __nv_bfloat16 *wth, *wtl;
    cudaGetSymbolAddress((void**)&hu,     g_hu);
    cudaGetSymbolAddress((void**)&ta,     g_ta);
    cudaGetSymbolAddress((void**)&ha2,    g_ha2);
    cudaGetSymbolAddress((void**)&meanA,  g_meanA);
    cudaGetSymbolAddress((void**)&meanU,  g_meanU);
    cudaGetSymbolAddress((void**)&meanA2, g_meanA2);
    cudaGetSymbolAddress((void**)&hag,    g_hag);
    cudaGetSymbolAddress((void**)&wth,    g_wt_hi);
    cudaGetSymbolAddress((void**)&wtl,    g_wt_lo);

    constexpr int SM_K1    = 69760;
    constexpr int SM_T64   = (2 * 64 + 2 * 128) * ASTR;       // 104448
    constexpr int SM_T128  = 4 * 128 * ASTR;                  // 139264

    cudaFuncSetAttribute((void*)k1_prep_stage1, cudaFuncAttributeMaxDynamicSharedMemorySize, SM_K1);
    cudaFuncSetAttribute((void*)k2_mixed,       cudaFuncAttributeMaxDynamicSharedMemorySize, SM_T128);
    cudaFuncSetAttribute((void*)k3_mixed,       cudaFuncAttributeMaxDynamicSharedMemorySize, SM_T64);
    cudaFuncSetAttribute((void*)gemm_triple,    cudaFuncAttributeMaxDynamicSharedMemorySize, SM_T128);

    const __nv_bfloat16 *WH0 = wth + 0*16384, *WL0 = wtl + 0*16384;   // aggr_a
    const __nv_bfloat16 *WH1 = wth + 1*16384, *WL1 = wtl + 1*16384;   // self_a
    const __nv_bfloat16 *WH2 = wth + 2*16384, *WL2 = wtl + 2*16384;   // comb_a
    const __nv_bfloat16 *WH3 = wth + 3*16384, *WL3 = wtl + 3*16384;   // aggr_u
    const __nv_bfloat16 *WH4 = wth + 4*16384, *WL4 = wtl + 4*16384;   // self_u
    const __nv_bfloat16 *WH5 = wth + 5*16384, *WL5 = wtl + 5*16384;   // comb_u
    const __nv_bfloat16 *WH6 = wth + 6*16384, *WL6 = wtl + 6*16384;   // W_norm'

    // 1) weight prep (blocks 0..6) + stage1 (blocks 7..38)
    k1_prep_stage1<<<7 + NUSER/128, 256, SM_K1>>>(
        (const float*)d_in[10], (const float*)d_in[12], (const float*)d_in[14],
        (const float*)d_in[16], (const float*)d_in[18], (const float*)d_in[20],
        W_norm, wth, wtl,
        user_feat, W_ue, b_ue, W_t, b_t, hu, hag);

    // 2) K2: agent {aggr_u -> meanU; self_a -> t_a raw}  ||  aggr16 -> meanA
    k2_mixed<<<148, 256, SM_T128>>>(noise, hag,
                                    WH3, WL3, b_aggr_u, meanU,
                                    WH1, WL1, b_self_a, ta,
                                    hu, WH0, WL0, b_aggr_a, meanA);

    // 3) K3: user triple -> meanA2  ||  comb_a(t_a + meanA) -> ha2
    k3_mixed<<<64 + NAG/64, 256, SM_T64>>>(hu,
                                           WH4, WL4, b_self_u, meanU,
                                           WH5, WL5, b_comb_u,
                                           WH0, WL0, b_aggr_a, meanA2,
                                           ta, meanA, WH2, WL2, b_comb_a, ha2);

    // 4) conv2 agent + final projection + normalize -> out
    gemm_triple<<<NAG/128, 256, SM_T128>>>(ha2, WH1, WL1, b_self_a, meanA2,
                                           WH2, WL2, b_comb_a, WH6, WL6, b_norm, out);
}